// round 4
// baseline (speedup 1.0000x reference)
#include <cuda_runtime.h>

// GAT 3-layer forward on GB300.
// Strategy: build CSR-by-dst once per launch (histogram + scan + scatter),
// then each layer = dense GEMM + per-node attention scores + warp-per-node
// online-softmax aggregation (atomic-free, float4 gathers, L2-resident tables).

#define NN   50000
#define EE   1600000
#define ET   (NN + EE)     // edges + self loops
#define HID  128
#define IND  13
#define OUTD 5

// ---------------- scratch (device globals; no allocation allowed) ----------
__device__ __align__(16) float g_hA[NN * HID];   // GEMM outputs (layer inputs to agg)
__device__ __align__(16) float g_hB[NN * HID];   // agg outputs (inputs to next GEMM)
__device__ __align__(16) float g_h3[NN * OUTD];  // layer-3 GEMM output
__device__ float g_as[NN];
__device__ float g_ad[NN];
__device__ int   g_deg[NN];
__device__ int   g_roff[NN + 1];
__device__ int   g_cur[NN];
__device__ int   g_csr[ET];
__device__ int   g_srcv[EE];
__device__ int   g_dstv[EE];
__device__ int   g_is64;

__device__ __forceinline__ float warp_sum(float v) {
#pragma unroll
    for (int o = 16; o > 0; o >>= 1) v += __shfl_xor_sync(0xffffffffu, v, o);
    return v;
}

// ---------------- edge dtype detect + normalize ----------------------------
// If edge_index is int64, every odd 32-bit word (high half) is 0 (values < 50000).
// If int32, odd words are random edge indices; all-zero over 32 samples ~ impossible.
__global__ void detect_kernel(const unsigned* __restrict__ w) {
    if (blockIdx.x == 0 && threadIdx.x == 0) {
        int all0 = 1;
        for (int i = 1; i < 64; i += 2) all0 &= (w[i] == 0u);
        g_is64 = all0;
    }
}

__global__ void convert_kernel(const void* __restrict__ ei, int E) {
    int i = blockIdx.x * blockDim.x + threadIdx.x;
    if (i >= E) return;
    if (g_is64) {
        const long long* p = (const long long*)ei;
        g_srcv[i] = (int)p[i];
        g_dstv[i] = (int)p[E + i];
    } else {
        const int* p = (const int*)ei;
        g_srcv[i] = p[i];
        g_dstv[i] = p[E + i];
    }
}

// ---------------- CSR build -------------------------------------------------
__global__ void init_deg_kernel(int n) {
    int i = blockIdx.x * blockDim.x + threadIdx.x;
    if (i < n) g_deg[i] = 1;  // self loop
}

__global__ void count_kernel(int E) {
    int i = blockIdx.x * blockDim.x + threadIdx.x;
    if (i < E) atomicAdd(&g_deg[g_dstv[i]], 1);
}

__global__ void scan_kernel(int n) {  // single block, 1024 threads
    __shared__ int part[1024];
    int tid = threadIdx.x;
    int chunk = (n + 1023) / 1024;
    int beg = tid * chunk;
    int end = beg + chunk; if (end > n) end = n;
    int s = 0;
    for (int i = beg; i < end; i++) s += g_deg[i];
    part[tid] = s;
    __syncthreads();
    for (int off = 1; off < 1024; off <<= 1) {
        int v = (tid >= off) ? part[tid - off] : 0;
        __syncthreads();
        part[tid] += v;
        __syncthreads();
    }
    int ex = (tid == 0) ? 0 : part[tid - 1];
    for (int i = beg; i < end; i++) {
        g_roff[i] = ex;
        g_cur[i]  = ex;
        ex += g_deg[i];
    }
    if (end == n && beg < n) g_roff[n] = ex;
}

__global__ void scatter_kernel(int E, int n) {
    int i = blockIdx.x * blockDim.x + threadIdx.x;
    int total = n + E;
    if (i >= total) return;
    int src, dst;
    if (i < n) { src = i; dst = i; }           // self loops
    else       { int e = i - n; src = g_srcv[e]; dst = g_dstv[e]; }
    int p = atomicAdd(&g_cur[dst], 1);
    g_csr[p] = src;
}

// ---------------- GEMMs -----------------------------------------------------
// Layer 1: [N,13] @ [13,128] -> g_hA
__global__ void gemm13_kernel(const float* __restrict__ x, const float* __restrict__ W) {
    __shared__ float Ws[IND * HID];
    __shared__ float xs[16 * IND];
    int tid = threadIdx.x;
    for (int j = tid; j < IND * HID; j += 128) Ws[j] = W[j];
    int base = blockIdx.x * 16;
    for (int j = tid; j < 16 * IND; j += 128) {
        int r = j / IND, k = j % IND;
        xs[j] = x[(base + r) * IND + k];
    }
    __syncthreads();
#pragma unroll 4
    for (int r = 0; r < 16; r++) {
        float acc = 0.f;
#pragma unroll
        for (int k = 0; k < IND; k++) acc += xs[r * IND + k] * Ws[k * HID + tid];
        g_hA[(base + r) * HID + tid] = acc;
    }
}

// Layer 2: g_hB [N,128] @ W2 [128,128] -> g_hA. Register-tiled, 16 rows/block.
__global__ void gemm128_kernel(const float* __restrict__ W) {
    __shared__ float4 hs[16 * 32];
    int tid = threadIdx.x;
    int base = blockIdx.x * 16;
    const float4* hin4 = (const float4*)g_hB;
    for (int j = tid; j < 512; j += 128) {
        int r = j >> 5, q = j & 31;
        hs[j] = hin4[(base + r) * 32 + q];
    }
    __syncthreads();
    float acc[16];
#pragma unroll
    for (int r = 0; r < 16; r++) acc[r] = 0.f;
    for (int k4 = 0; k4 < 32; k4++) {
        float w0 = __ldg(&W[(4 * k4 + 0) * HID + tid]);
        float w1 = __ldg(&W[(4 * k4 + 1) * HID + tid]);
        float w2 = __ldg(&W[(4 * k4 + 2) * HID + tid]);
        float w3 = __ldg(&W[(4 * k4 + 3) * HID + tid]);
#pragma unroll
        for (int r = 0; r < 16; r++) {
            float4 hv = hs[r * 32 + k4];
            acc[r] += hv.x * w0 + hv.y * w1 + hv.z * w2 + hv.w * w3;
        }
    }
#pragma unroll
    for (int r = 0; r < 16; r++) g_hA[(base + r) * HID + tid] = acc[r];
}

// ---------------- attention scores (as = h.a_src, ad = h.a_dst) -------------
__global__ void attn128_kernel(const float* __restrict__ a_s, const float* __restrict__ a_d) {
    int warp = (blockIdx.x * blockDim.x + threadIdx.x) >> 5;
    int lane = threadIdx.x & 31;
    if (warp >= NN) return;
    const float4* h4 = (const float4*)g_hA;
    float4 hv = h4[warp * 32 + lane];
    float4 s4 = ((const float4*)a_s)[lane];
    float4 d4 = ((const float4*)a_d)[lane];
    float ps = hv.x * s4.x + hv.y * s4.y + hv.z * s4.z + hv.w * s4.w;
    float pd = hv.x * d4.x + hv.y * d4.y + hv.z * d4.z + hv.w * d4.w;
    ps = warp_sum(ps);
    pd = warp_sum(pd);
    if (lane == 0) { g_as[warp] = ps; g_ad[warp] = pd; }
}

// ---------------- 128-dim softmax aggregation (warp per node) ---------------
// reads g_hA, writes relu(agg + bias) into g_hB
__global__ void agg128_kernel(const float* __restrict__ bias) {
    int warp = (blockIdx.x * blockDim.x + threadIdx.x) >> 5;
    int lane = threadIdx.x & 31;
    if (warp >= NN) return;
    int start = g_roff[warp], end = g_roff[warp + 1];
    float adi = g_ad[warp];

    // pass 1: online softmax (max + sum), lanes stride the edge list
    float m = -1e30f, s = 0.f;
    for (int e = start + lane; e < end; e += 32) {
        int src = g_csr[e];
        float ev = g_as[src] + adi;
        ev = ev > 0.f ? ev : 0.2f * ev;
        float mn = fmaxf(m, ev);
        s = s * __expf(m - mn) + __expf(ev - mn);
        m = mn;
    }
#pragma unroll
    for (int o = 16; o > 0; o >>= 1) {
        float mo = __shfl_xor_sync(0xffffffffu, m, o);
        float so = __shfl_xor_sync(0xffffffffu, s, o);
        float mn = fmaxf(m, mo);
        s = s * __expf(m - mn) + so * __expf(mo - mn);
        m = mn;
    }
    float inv = 1.f / (s + 1e-16f);

    // pass 2: weighted gather-accumulate; warp cooperates per edge (1 float4/lane)
    const float4* h4 = (const float4*)g_hA;
    float4 acc = make_float4(0.f, 0.f, 0.f, 0.f);
    int e = start;
    for (; e + 1 < end; e += 2) {
        int s0 = g_csr[e], s1 = g_csr[e + 1];
        float4 h0 = h4[s0 * 32 + lane];
        float4 h1 = h4[s1 * 32 + lane];
        float e0 = g_as[s0] + adi; e0 = e0 > 0.f ? e0 : 0.2f * e0;
        float e1 = g_as[s1] + adi; e1 = e1 > 0.f ? e1 : 0.2f * e1;
        float w0 = __expf(e0 - m) * inv;
        float w1 = __expf(e1 - m) * inv;
        acc.x += w0 * h0.x + w1 * h1.x;
        acc.y += w0 * h0.y + w1 * h1.y;
        acc.z += w0 * h0.z + w1 * h1.z;
        acc.w += w0 * h0.w + w1 * h1.w;
    }
    if (e < end) {
        int s0 = g_csr[e];
        float4 h0 = h4[s0 * 32 + lane];
        float e0 = g_as[s0] + adi; e0 = e0 > 0.f ? e0 : 0.2f * e0;
        float w0 = __expf(e0 - m) * inv;
        acc.x += w0 * h0.x; acc.y += w0 * h0.y; acc.z += w0 * h0.z; acc.w += w0 * h0.w;
    }

    float4 b4 = ((const float4*)bias)[lane];
    acc.x = fmaxf(acc.x + b4.x, 0.f);
    acc.y = fmaxf(acc.y + b4.y, 0.f);
    acc.z = fmaxf(acc.z + b4.z, 0.f);
    acc.w = fmaxf(acc.w + b4.w, 0.f);
    ((float4*)g_hB)[warp * 32 + lane] = acc;
}

// ---------------- layer 3 GEMM (128->5) fused with scores -------------------
__global__ void l3_kernel(const float* __restrict__ W3,
                          const float* __restrict__ a_s, const float* __restrict__ a_d) {
    __shared__ float Ws[HID * OUTD];
    int tid = threadIdx.x;
    for (int j = tid; j < HID * OUTD; j += blockDim.x) Ws[j] = W3[j];
    __syncthreads();
    int warp = (blockIdx.x * blockDim.x + tid) >> 5;
    int lane = tid & 31;
    if (warp >= NN) return;
    const float4* h4 = (const float4*)g_hB;
    float4 hv = h4[warp * 32 + lane];
    int k = 4 * lane;
    float o[OUTD];
#pragma unroll
    for (int c = 0; c < OUTD; c++) {
        float p = hv.x * Ws[(k + 0) * OUTD + c] + hv.y * Ws[(k + 1) * OUTD + c]
                + hv.z * Ws[(k + 2) * OUTD + c] + hv.w * Ws[(k + 3) * OUTD + c];
        o[c] = warp_sum(p);
    }
    if (lane == 0) {
        float as = 0.f, ad = 0.f;
#pragma unroll
        for (int c = 0; c < OUTD; c++) {
            g_h3[warp * OUTD + c] = o[c];
            as += o[c] * a_s[c];
            ad += o[c] * a_d[c];
        }
        g_as[warp] = as;
        g_ad[warp] = ad;
    }
}

// ---------------- 5-dim aggregation + log_softmax -> d_out ------------------
__global__ void agg5_kernel(const float* __restrict__ b3, float* __restrict__ out) {
    int warp = (blockIdx.x * blockDim.x + threadIdx.x) >> 5;
    int lane = threadIdx.x & 31;
    if (warp >= NN) return;
    int start = g_roff[warp], end = g_roff[warp + 1];
    float adi = g_ad[warp];

    float m = -1e30f, s = 0.f;
    for (int e = start + lane; e < end; e += 32) {
        int src = g_csr[e];
        float ev = g_as[src] + adi;
        ev = ev > 0.f ? ev : 0.2f * ev;
        float mn = fmaxf(m, ev);
        s = s * __expf(m - mn) + __expf(ev - mn);
        m = mn;
    }
#pragma unroll
    for (int o = 16; o > 0; o >>= 1) {
        float mo = __shfl_xor_sync(0xffffffffu, m, o);
        float so = __shfl_xor_sync(0xffffffffu, s, o);
        float mn = fmaxf(m, mo);
        s = s * __expf(m - mn) + so * __expf(mo - mn);
        m = mn;
    }
    float inv = 1.f / (s + 1e-16f);

    float acc = 0.f;
    int e = start;
    for (; e + 1 < end; e += 2) {
        int s0 = g_csr[e], s1 = g_csr[e + 1];
        float e0 = g_as[s0] + adi; e0 = e0 > 0.f ? e0 : 0.2f * e0;
        float e1 = g_as[s1] + adi; e1 = e1 > 0.f ? e1 : 0.2f * e1;
        float w0 = __expf(e0 - m) * inv;
        float w1 = __expf(e1 - m) * inv;
        if (lane < OUTD) acc += w0 * g_h3[s0 * OUTD + lane] + w1 * g_h3[s1 * OUTD + lane];
    }
    if (e < end) {
        int s0 = g_csr[e];
        float e0 = g_as[s0] + adi; e0 = e0 > 0.f ? e0 : 0.2f * e0;
        float w0 = __expf(e0 - m) * inv;
        if (lane < OUTD) acc += w0 * g_h3[s0 * OUTD + lane];
    }

    float v = (lane < OUTD) ? (acc + b3[lane]) : -1e30f;
    // log_softmax across lanes 0..4 (xor over a group of 8)
    float m5 = v;
#pragma unroll
    for (int o = 4; o > 0; o >>= 1) m5 = fmaxf(m5, __shfl_xor_sync(0xffffffffu, m5, o));
    float ex = (lane < OUTD) ? __expf(v - m5) : 0.f;
#pragma unroll
    for (int o = 4; o > 0; o >>= 1) ex += __shfl_xor_sync(0xffffffffu, ex, o);
    if (lane < OUTD) out[warp * OUTD + lane] = v - m5 - logf(ex);
}

// ---------------- launch ----------------------------------------------------
extern "C" void kernel_launch(void* const* d_in, const int* in_sizes, int n_in,
                              void* d_out, int out_size) {
    const float* x      = (const float*)d_in[0];
    const void*  ei     = d_in[1];
    const float* W1     = (const float*)d_in[2];
    const float* a_src1 = (const float*)d_in[3];
    const float* a_dst1 = (const float*)d_in[4];
    const float* b1     = (const float*)d_in[5];
    const float* W2     = (const float*)d_in[6];
    const float* a_src2 = (const float*)d_in[7];
    const float* a_dst2 = (const float*)d_in[8];
    const float* b2     = (const float*)d_in[9];
    const float* W3     = (const float*)d_in[10];
    const float* a_src3 = (const float*)d_in[11];
    const float* a_dst3 = (const float*)d_in[12];
    const float* b3     = (const float*)d_in[13];
    float* out = (float*)d_out;

    const int E = in_sizes[1] / 2;  // 1,600,000 regardless of int32/int64
    const int N = NN;

    // CSR build
    detect_kernel<<<1, 32>>>((const unsigned*)ei);
    convert_kernel<<<(E + 255) / 256, 256>>>(ei, E);
    init_deg_kernel<<<(N + 255) / 256, 256>>>(N);
    count_kernel<<<(E + 255) / 256, 256>>>(E);
    scan_kernel<<<1, 1024>>>(N);
    scatter_kernel<<<(N + E + 255) / 256, 256>>>(E, N);

    // Layer 1
    gemm13_kernel<<<N / 16, 128>>>(x, W1);
    attn128_kernel<<<N / 8, 256>>>(a_src1, a_dst1);
    agg128_kernel<<<N / 8, 256>>>(b1);

    // Layer 2
    gemm128_kernel<<<N / 16, 128>>>(W2);
    attn128_kernel<<<N / 8, 256>>>(a_src2, a_dst2);
    agg128_kernel<<<N / 8, 256>>>(b2);

    // Layer 3
    l3_kernel<<<N / 8, 256>>>(W3, a_src3, a_dst3);
    agg5_kernel<<<N / 8, 256>>>(b3, out);
}

// round 6
// speedup vs baseline: 1.3970x; 1.3970x over previous
#include <cuda_runtime.h>

// GAT 3-layer forward on GB300.
// CSR-by-dst build (fused histogram + parallel 2-level scan + scatter), then
// per layer: dense GEMM (f32x2-packed FFMA for the 128x128 layer) + per-node
// attention scores + warp-per-node single-pass softmax aggregation
// (unnormalized exp — mathematically identical to max-subtracted softmax).

#define NN   50000
#define EE   1600000
#define ET   (NN + EE)     // edges + self loops
#define HID  128
#define IND  13
#define OUTD 5
#define NB   196           // ceil(NN/256)

// ---------------- scratch (device globals; no allocation allowed) ----------
__device__ __align__(16) float g_hA[NN * HID];
__device__ __align__(16) float g_hB[NN * HID];
__device__ __align__(16) float g_h3[NN * OUTD];
__device__ float g_as[NN];
__device__ float g_ad[NN];
__device__ int   g_deg[NN];
__device__ int   g_roff[NN + 1];
__device__ int   g_cur[NN];
__device__ int   g_csr[ET];
__device__ int   g_srcv[EE];
__device__ int   g_dstv[EE];
__device__ int   g_bsum[256];
__device__ int   g_boff[256];
__device__ int   g_is64;

#define FMA_F32X2(d, a, b, c) \
    asm("fma.rn.f32x2 %0, %1, %2, %3;" : "=l"(d) : "l"(a), "l"(b), "l"(c))

__device__ __forceinline__ unsigned long long pack_f32x2(float lo, float hi) {
    unsigned long long r;
    unsigned ulo = __float_as_uint(lo), uhi = __float_as_uint(hi);
    asm("mov.b64 %0, {%1, %2};" : "=l"(r) : "r"(ulo), "r"(uhi));
    return r;
}
__device__ __forceinline__ void unpack_f32x2(unsigned long long v, float& lo, float& hi) {
    unsigned ulo, uhi;
    asm("mov.b64 {%0, %1}, %2;" : "=r"(ulo), "=r"(uhi) : "l"(v));
    lo = __uint_as_float(ulo);
    hi = __uint_as_float(uhi);
}

__device__ __forceinline__ float warp_sum(float v) {
#pragma unroll
    for (int o = 16; o > 0; o >>= 1) v += __shfl_xor_sync(0xffffffffu, v, o);
    return v;
}
__device__ __forceinline__ float lrelu(float v) { return v > 0.f ? v : 0.2f * v; }

// ---------------- edge dtype detect + normalize + degree histogram ----------
__global__ void detect_kernel(const unsigned* __restrict__ w) {
    if (blockIdx.x == 0 && threadIdx.x == 0) {
        int all0 = 1;
        for (int i = 1; i < 64; i += 2) all0 &= (w[i] == 0u);
        g_is64 = all0;
    }
}

__global__ void init_deg_kernel(int n) {
    int i = blockIdx.x * blockDim.x + threadIdx.x;
    if (i < n) g_deg[i] = 1;  // self loop
}

__global__ void convert_count_kernel(const void* __restrict__ ei, int E) {
    int i = blockIdx.x * blockDim.x + threadIdx.x;
    if (i >= E) return;
    int s, d;
    if (g_is64) {
        const long long* p = (const long long*)ei;
        s = (int)p[i];
        d = (int)p[E + i];
    } else {
        const int* p = (const int*)ei;
        s = p[i];
        d = p[E + i];
    }
    g_srcv[i] = s;
    g_dstv[i] = d;
    atomicAdd(&g_deg[d], 1);
}

// ---------------- two-level parallel exclusive scan of g_deg ----------------
__global__ void scan1_kernel() {
    int i = blockIdx.x * 256 + threadIdx.x;
    int v = (i < NN) ? g_deg[i] : 0;
#pragma unroll
    for (int o = 16; o > 0; o >>= 1) v += __shfl_xor_sync(0xffffffffu, v, o);
    __shared__ int sw[8];
    if ((threadIdx.x & 31) == 0) sw[threadIdx.x >> 5] = v;
    __syncthreads();
    if (threadIdx.x == 0) {
        int t = 0;
#pragma unroll
        for (int k = 0; k < 8; k++) t += sw[k];
        g_bsum[blockIdx.x] = t;
    }
}

__global__ void scan2_kernel(int E) {
    __shared__ int sh[256];
    int tid = threadIdx.x;
    int v = (tid < NB) ? g_bsum[tid] : 0;
    sh[tid] = v;
    __syncthreads();
    for (int off = 1; off < 256; off <<= 1) {
        int t = (tid >= off) ? sh[tid - off] : 0;
        __syncthreads();
        sh[tid] += t;
        __syncthreads();
    }
    g_boff[tid] = sh[tid] - v;  // exclusive
    if (tid == 0) g_roff[NN] = NN + E;
}

__global__ void scan3_kernel() {
    __shared__ int sh[256];
    int tid = threadIdx.x;
    int i = blockIdx.x * 256 + tid;
    int v = (i < NN) ? g_deg[i] : 0;
    sh[tid] = v;
    __syncthreads();
    for (int off = 1; off < 256; off <<= 1) {
        int t = (tid >= off) ? sh[tid - off] : 0;
        __syncthreads();
        sh[tid] += t;
        __syncthreads();
    }
    if (i < NN) {
        int o = g_boff[blockIdx.x] + sh[tid] - v;
        g_roff[i] = o;
        g_cur[i]  = o;
    }
}

__global__ void scatter_kernel(int E, int n) {
    int i = blockIdx.x * blockDim.x + threadIdx.x;
    int total = n + E;
    if (i >= total) return;
    int src, dst;
    if (i < n) { src = i; dst = i; }
    else       { int e = i - n; src = g_srcv[e]; dst = g_dstv[e]; }
    int p = atomicAdd(&g_cur[dst], 1);
    g_csr[p] = src;
}

// ---------------- GEMMs -----------------------------------------------------
// Layer 1: [N,13] @ [13,128] -> g_hA
__global__ void gemm13_kernel(const float* __restrict__ x, const float* __restrict__ W) {
    __shared__ float Ws[IND * HID];
    __shared__ float xs[16 * IND];
    int tid = threadIdx.x;
    for (int j = tid; j < IND * HID; j += 128) Ws[j] = W[j];
    int base = blockIdx.x * 16;
    for (int j = tid; j < 16 * IND; j += 128) {
        int r = j / IND, k = j % IND;
        xs[j] = x[(base + r) * IND + k];
    }
    __syncthreads();
#pragma unroll 4
    for (int r = 0; r < 16; r++) {
        float acc = 0.f;
#pragma unroll
        for (int k = 0; k < IND; k++) acc += xs[r * IND + k] * Ws[k * HID + tid];
        g_hA[(base + r) * HID + tid] = acc;
    }
}

// Layer 2: g_hB [N,128] @ W2 [128,128] -> g_hA.
// f32x2 packed over adjacent K: FFMA2 halves fp32 issue count, bit-exact fp32.
#define GROWS 32
__global__ void __launch_bounds__(128) gemm128_kernel(const float* __restrict__ W) {
    __shared__ __align__(16) float hs[GROWS * HID];  // row-major [r][k], 16KB
    int tid = threadIdx.x;
    int base = blockIdx.x * GROWS;
    const float4* hin4 = (const float4*)g_hB;
    float4* hs4 = (float4*)hs;
    for (int j = tid; j < GROWS * 32; j += 128) {
        int r = j >> 5, q = j & 31;
        int row = base + r;
        hs4[j] = (row < NN) ? hin4[row * 32 + q] : make_float4(0.f, 0.f, 0.f, 0.f);
    }
    __syncthreads();

    unsigned long long acc[GROWS];
#pragma unroll
    for (int r = 0; r < GROWS; r++) acc[r] = 0ull;

    for (int kq = 0; kq < 32; kq++) {  // 4 K-values per iteration
        int k0 = 4 * kq;
        float w0 = __ldg(&W[(k0 + 0) * HID + tid]);
        float w1 = __ldg(&W[(k0 + 1) * HID + tid]);
        float w2 = __ldg(&W[(k0 + 2) * HID + tid]);
        float w3 = __ldg(&W[(k0 + 3) * HID + tid]);
        unsigned long long b01 = pack_f32x2(w0, w1);
        unsigned long long b23 = pack_f32x2(w2, w3);
#pragma unroll
        for (int r = 0; r < GROWS; r++) {
            // (h[r][k0],h[r][k0+1]) , (h[r][k0+2],h[r][k0+3]) — one LDS.128 broadcast
            const ulonglong2 a = *(const ulonglong2*)&hs[r * HID + k0];
            FMA_F32X2(acc[r], a.x, b01, acc[r]);
            FMA_F32X2(acc[r], a.y, b23, acc[r]);
        }
    }
#pragma unroll
    for (int r = 0; r < GROWS; r++) {
        if (base + r < NN) {
            float lo, hi;
            unpack_f32x2(acc[r], lo, hi);
            g_hA[(base + r) * HID + tid] = lo + hi;  // even-k partial + odd-k partial
        }
    }
}

// ---------------- attention scores (as = h.a_src, ad = h.a_dst) -------------
__global__ void attn128_kernel(const float* __restrict__ a_s, const float* __restrict__ a_d) {
    int warp = (blockIdx.x * blockDim.x + threadIdx.x) >> 5;
    int lane = threadIdx.x & 31;
    if (warp >= NN) return;
    const float4* h4 = (const float4*)g_hA;
    float4 hv = h4[warp * 32 + lane];
    float4 s4 = ((const float4*)a_s)[lane];
    float4 d4 = ((const float4*)a_d)[lane];
    float ps = hv.x * s4.x + hv.y * s4.y + hv.z * s4.z + hv.w * s4.w;
    float pd = hv.x * d4.x + hv.y * d4.y + hv.z * d4.z + hv.w * d4.w;
    ps = warp_sum(ps);
    pd = warp_sum(pd);
    if (lane == 0) { g_as[warp] = ps; g_ad[warp] = pd; }
}

// ---------------- 128-dim softmax aggregation, single pass ------------------
// alpha = exp(e)/sum exp(e); identical to max-subtracted softmax (scores O(1),
// clamp at 80 keeps exp finite in all cases). reads g_hA, writes g_hB.
__global__ void agg128_kernel(const float* __restrict__ bias) {
    int warp = (blockIdx.x * blockDim.x + threadIdx.x) >> 5;
    int lane = threadIdx.x & 31;
    if (warp >= NN) return;
    int e = g_roff[warp], end = g_roff[warp + 1];
    float adi = g_ad[warp];
    const float4* h4 = (const float4*)g_hA;

    float s = 0.f;
    float4 acc = make_float4(0.f, 0.f, 0.f, 0.f);
    for (; e + 3 < end; e += 4) {
        int s0 = g_csr[e], s1 = g_csr[e + 1], s2 = g_csr[e + 2], s3 = g_csr[e + 3];
        float4 h0 = h4[s0 * 32 + lane];
        float4 h1 = h4[s1 * 32 + lane];
        float4 h2 = h4[s2 * 32 + lane];
        float4 h3 = h4[s3 * 32 + lane];
        float w0 = __expf(fminf(lrelu(g_as[s0] + adi), 80.f));
        float w1 = __expf(fminf(lrelu(g_as[s1] + adi), 80.f));
        float w2 = __expf(fminf(lrelu(g_as[s2] + adi), 80.f));
        float w3 = __expf(fminf(lrelu(g_as[s3] + adi), 80.f));
        s += (w0 + w1) + (w2 + w3);
        acc.x += w0 * h0.x + w1 * h1.x + w2 * h2.x + w3 * h3.x;
        acc.y += w0 * h0.y + w1 * h1.y + w2 * h2.y + w3 * h3.y;
        acc.z += w0 * h0.z + w1 * h1.z + w2 * h2.z + w3 * h3.z;
        acc.w += w0 * h0.w + w1 * h1.w + w2 * h2.w + w3 * h3.w;
    }
    for (; e < end; e++) {
        int s0 = g_csr[e];
        float4 h0 = h4[s0 * 32 + lane];
        float w0 = __expf(fminf(lrelu(g_as[s0] + adi), 80.f));
        s += w0;
        acc.x += w0 * h0.x; acc.y += w0 * h0.y;
        acc.z += w0 * h0.z; acc.w += w0 * h0.w;
    }

    float inv = 1.f / s;
    float4 b4 = ((const float4*)bias)[lane];
    acc.x = fmaxf(acc.x * inv + b4.x, 0.f);
    acc.y = fmaxf(acc.y * inv + b4.y, 0.f);
    acc.z = fmaxf(acc.z * inv + b4.z, 0.f);
    acc.w = fmaxf(acc.w * inv + b4.w, 0.f);
    ((float4*)g_hB)[warp * 32 + lane] = acc;
}

// ---------------- layer 3 GEMM (128->5) fused with scores -------------------
__global__ void l3_kernel(const float* __restrict__ W3,
                          const float* __restrict__ a_s, const float* __restrict__ a_d) {
    __shared__ float Ws[HID * OUTD];
    int tid = threadIdx.x;
    for (int j = tid; j < HID * OUTD; j += blockDim.x) Ws[j] = W3[j];
    __syncthreads();
    int warp = (blockIdx.x * blockDim.x + tid) >> 5;
    int lane = tid & 31;
    if (warp >= NN) return;
    const float4* h4 = (const float4*)g_hB;
    float4 hv = h4[warp * 32 + lane];
    int k = 4 * lane;
    float o[OUTD];
#pragma unroll
    for (int c = 0; c < OUTD; c++) {
        float p = hv.x * Ws[(k + 0) * OUTD + c] + hv.y * Ws[(k + 1) * OUTD + c]
                + hv.z * Ws[(k + 2) * OUTD + c] + hv.w * Ws[(k + 3) * OUTD + c];
        o[c] = warp_sum(p);
    }
    if (lane == 0) {
        float as = 0.f, ad = 0.f;
#pragma unroll
        for (int c = 0; c < OUTD; c++) {
            g_h3[warp * OUTD + c] = o[c];
            as += o[c] * a_s[c];
            ad += o[c] * a_d[c];
        }
        g_as[warp] = as;
        g_ad[warp] = ad;
    }
}

// ---------------- 5-dim aggregation + log_softmax -> d_out ------------------
__global__ void agg5_kernel(const float* __restrict__ b3, float* __restrict__ out) {
    int warp = (blockIdx.x * blockDim.x + threadIdx.x) >> 5;
    int lane = threadIdx.x & 31;
    if (warp >= NN) return;
    int e = g_roff[warp], end = g_roff[warp + 1];
    float adi = g_ad[warp];

    float s = 0.f, acc = 0.f;
    for (; e + 1 < end; e += 2) {
        int s0 = g_csr[e], s1 = g_csr[e + 1];
        float w0 = __expf(fminf(lrelu(g_as[s0] + adi), 80.f));
        float w1 = __expf(fminf(lrelu(g_as[s1] + adi), 80.f));
        s += w0 + w1;
        if (lane < OUTD) acc += w0 * g_h3[s0 * OUTD + lane] + w1 * g_h3[s1 * OUTD + lane];
    }
    if (e < end) {
        int s0 = g_csr[e];
        float w0 = __expf(fminf(lrelu(g_as[s0] + adi), 80.f));
        s += w0;
        if (lane < OUTD) acc += w0 * g_h3[s0 * OUTD + lane];
    }

    float v = (lane < OUTD) ? (acc / s + b3[lane]) : -1e30f;
    float m5 = v;
#pragma unroll
    for (int o = 4; o > 0; o >>= 1) m5 = fmaxf(m5, __shfl_xor_sync(0xffffffffu, m5, o));
    float ex = (lane < OUTD) ? __expf(v - m5) : 0.f;
#pragma unroll
    for (int o = 4; o > 0; o >>= 1) ex += __shfl_xor_sync(0xffffffffu, ex, o);
    if (lane < OUTD) out[warp * OUTD + lane] = v - m5 - logf(ex);
}

// ---------------- launch ----------------------------------------------------
extern "C" void kernel_launch(void* const* d_in, const int* in_sizes, int n_in,
                              void* d_out, int out_size) {
    const float* x      = (const float*)d_in[0];
    const void*  ei     = d_in[1];
    const float* W1     = (const float*)d_in[2];
    const float* a_src1 = (const float*)d_in[3];
    const float* a_dst1 = (const float*)d_in[4];
    const float* b1     = (const float*)d_in[5];
    const float* W2     = (const float*)d_in[6];
    const float* a_src2 = (const float*)d_in[7];
    const float* a_dst2 = (const float*)d_in[8];
    const float* b2     = (const float*)d_in[9];
    const float* W3     = (const float*)d_in[10];
    const float* a_src3 = (const float*)d_in[11];
    const float* a_dst3 = (const float*)d_in[12];
    const float* b3     = (const float*)d_in[13];
    float* out = (float*)d_out;

    const int E = in_sizes[1] / 2;
    const int N = NN;

    // CSR build
    detect_kernel<<<1, 32>>>((const unsigned*)ei);
    init_deg_kernel<<<NB, 256>>>(N);
    convert_count_kernel<<<(E + 255) / 256, 256>>>(ei, E);
    scan1_kernel<<<NB, 256>>>();
    scan2_kernel<<<1, 256>>>(E);
    scan3_kernel<<<NB, 256>>>();
    scatter_kernel<<<(N + E + 255) / 256, 256>>>(E, N);

    // Layer 1
    gemm13_kernel<<<N / 16, 128>>>(x, W1);
    attn128_kernel<<<N / 8, 256>>>(a_src1, a_dst1);
    agg128_kernel<<<N / 8, 256>>>(b1);

    // Layer 2
    gemm128_kernel<<<(N + GROWS - 1) / GROWS, 128>>>(W2);
    attn128_kernel<<<N / 8, 256>>>(a_src2, a_dst2);
    agg128_kernel<<<N / 8, 256>>>(b2);

    // Layer 3
    l3_kernel<<<N / 8, 256>>>(W3, a_src3, a_dst3);
    agg5_kernel<<<N / 8, 256>>>(b3, out);
}

// round 9
// speedup vs baseline: 1.4454x; 1.0347x over previous
#include <cuda_runtime.h>
#include <cuda_fp16.h>

// GAT 3-layer forward on GB300.
// CSR-by-dst build, then per layer: dense GEMM with fused attention-score
// epilogue (emits fp16 features for the edge gathers + fp32 scores), and
// warp-per-node single-pass softmax aggregation over fp16 features with
// fp32 accumulation (weighted average -> fp16 storage error stays ~1e-4).

#define NN   50000
#define EE   1600000
#define ET   (NN + EE)     // edges + self loops
#define HID  128
#define IND  13
#define OUTD 5
#define NB   196           // ceil(NN/256)

// ---------------- scratch (device globals; no allocation allowed) ----------
__device__ __align__(16) __half g_h16[NN * HID];  // fp16 features for gathers
__device__ __align__(16) float g_hB[NN * HID];    // fp32 agg outputs / GEMM inputs
__device__ __align__(16) float g_h3[NN * OUTD];
__device__ float g_as[NN];
__device__ float g_ad[NN];
__device__ int   g_deg[NN];
__device__ int   g_roff[NN + 1];
__device__ int   g_cur[NN];
__device__ int   g_csr[ET];
__device__ int   g_srcv[EE];
__device__ int   g_dstv[EE];
__device__ int   g_bsum[256];
__device__ int   g_boff[256];
__device__ int   g_is64;

#define FMA_F32X2(d, a, b, c) \
    asm("fma.rn.f32x2 %0, %1, %2, %3;" : "=l"(d) : "l"(a), "l"(b), "l"(c))

__device__ __forceinline__ unsigned long long pack_f32x2(float lo, float hi) {
    unsigned long long r;
    unsigned ulo = __float_as_uint(lo), uhi = __float_as_uint(hi);
    asm("mov.b64 %0, {%1, %2};" : "=l"(r) : "r"(ulo), "r"(uhi));
    return r;
}
__device__ __forceinline__ void unpack_f32x2(unsigned long long v, float& lo, float& hi) {
    unsigned ulo, uhi;
    asm("mov.b64 {%0, %1}, %2;" : "=r"(ulo), "=r"(uhi) : "l"(v));
    lo = __uint_as_float(ulo);
    hi = __uint_as_float(uhi);
}

__device__ __forceinline__ float warp_sum(float v) {
#pragma unroll
    for (int o = 16; o > 0; o >>= 1) v += __shfl_xor_sync(0xffffffffu, v, o);
    return v;
}
__device__ __forceinline__ float lrelu(float v) { return v > 0.f ? v : 0.2f * v; }

// ---------------- detect edge dtype + init degrees (fused) ------------------
__global__ void init_kernel(const unsigned* __restrict__ w, int n) {
    int i = blockIdx.x * blockDim.x + threadIdx.x;
    if (i < n) g_deg[i] = 1;  // self loop
    if (blockIdx.x == 0 && threadIdx.x == 0) {
        int all0 = 1;
        for (int k = 1; k < 64; k += 2) all0 &= (w[k] == 0u);
        g_is64 = all0;
    }
}

__global__ void convert_count_kernel(const void* __restrict__ ei, int E) {
    int i = blockIdx.x * blockDim.x + threadIdx.x;
    if (i >= E) return;
    int s, d;
    if (g_is64) {
        const long long* p = (const long long*)ei;
        s = (int)p[i];
        d = (int)p[E + i];
    } else {
        const int* p = (const int*)ei;
        s = p[i];
        d = p[E + i];
    }
    g_srcv[i] = s;
    g_dstv[i] = d;
    atomicAdd(&g_deg[d], 1);
}

// ---------------- two-level parallel exclusive scan of g_deg ----------------
__global__ void scan1_kernel() {
    int i = blockIdx.x * 256 + threadIdx.x;
    int v = (i < NN) ? g_deg[i] : 0;
#pragma unroll
    for (int o = 16; o > 0; o >>= 1) v += __shfl_xor_sync(0xffffffffu, v, o);
    __shared__ int sw[8];
    if ((threadIdx.x & 31) == 0) sw[threadIdx.x >> 5] = v;
    __syncthreads();
    if (threadIdx.x == 0) {
        int t = 0;
#pragma unroll
        for (int k = 0; k < 8; k++) t += sw[k];
        g_bsum[blockIdx.x] = t;
    }
}

__global__ void scan2_kernel(int E) {
    __shared__ int sh[256];
    int tid = threadIdx.x;
    int v = (tid < NB) ? g_bsum[tid] : 0;
    sh[tid] = v;
    __syncthreads();
    for (int off = 1; off < 256; off <<= 1) {
        int t = (tid >= off) ? sh[tid - off] : 0;
        __syncthreads();
        sh[tid] += t;
        __syncthreads();
    }
    g_boff[tid] = sh[tid] - v;  // exclusive
    if (tid == 0) g_roff[NN] = NN + E;
}

__global__ void scan3_kernel() {
    __shared__ int sh[256];
    int tid = threadIdx.x;
    int i = blockIdx.x * 256 + tid;
    int v = (i < NN) ? g_deg[i] : 0;
    sh[tid] = v;
    __syncthreads();
    for (int off = 1; off < 256; off <<= 1) {
        int t = (tid >= off) ? sh[tid - off] : 0;
        __syncthreads();
        sh[tid] += t;
        __syncthreads();
    }
    if (i < NN) {
        int o = g_boff[blockIdx.x] + sh[tid] - v;
        g_roff[i] = o;
        g_cur[i]  = o;
    }
}

__global__ void scatter_kernel(int E, int n) {
    int i = blockIdx.x * blockDim.x + threadIdx.x;
    int total = n + E;
    if (i >= total) return;
    int src, dst;
    if (i < n) { src = i; dst = i; }
    else       { int e = i - n; src = g_srcv[e]; dst = g_dstv[e]; }
    int p = atomicAdd(&g_cur[dst], 1);
    g_csr[p] = src;
}

// ---------------- GEMMs with fused score epilogue ---------------------------
// Layer 1: [N,13] @ [13,128] -> g_h16 (+ scores g_as/g_ad)
__global__ void gemm13_kernel(const float* __restrict__ x, const float* __restrict__ W,
                              const float* __restrict__ a_s, const float* __restrict__ a_d) {
    __shared__ float Ws[IND * HID];
    __shared__ float xs[16 * IND];
    __shared__ __align__(16) float hs[16 * HID];
    int tid = threadIdx.x;
    for (int j = tid; j < IND * HID; j += 128) Ws[j] = W[j];
    int base = blockIdx.x * 16;
    for (int j = tid; j < 16 * IND; j += 128) {
        int r = j / IND, k = j % IND;
        xs[j] = x[(base + r) * IND + k];
    }
    __syncthreads();
#pragma unroll 4
    for (int r = 0; r < 16; r++) {
        float acc = 0.f;
#pragma unroll
        for (int k = 0; k < IND; k++) acc += xs[r * IND + k] * Ws[k * HID + tid];
        g_h16[(base + r) * HID + tid] = __float2half(acc);
        hs[r * HID + tid] = acc;
    }
    __syncthreads();
    // scores: 4 warps x 4 rows each
    int wid = tid >> 5, lane = tid & 31;
    float4 s4 = ((const float4*)a_s)[lane];
    float4 d4 = ((const float4*)a_d)[lane];
#pragma unroll
    for (int i = 0; i < 4; i++) {
        int r = wid * 4 + i;
        float4 hv = ((const float4*)(hs + r * HID))[lane];
        float ps = hv.x * s4.x + hv.y * s4.y + hv.z * s4.z + hv.w * s4.w;
        float pd = hv.x * d4.x + hv.y * d4.y + hv.z * d4.z + hv.w * d4.w;
        ps = warp_sum(ps);
        pd = warp_sum(pd);
        if (lane == 0) { g_as[base + r] = ps; g_ad[base + r] = pd; }
    }
}

// Layer 2: g_hB [N,128] @ W2 [128,128] -> g_h16 (+ scores).
// f32x2 packed over adjacent K halves the FFMA issue count (bit-exact fp32).
#define GROWS 32
__global__ void __launch_bounds__(128) gemm128_kernel(const float* __restrict__ W,
                                                      const float* __restrict__ a_s,
                                                      const float* __restrict__ a_d) {
    __shared__ __align__(16) float hs[GROWS * HID];  // 16KB, reused for epilogue
    int tid = threadIdx.x;
    int base = blockIdx.x * GROWS;
    const float4* hin4 = (const float4*)g_hB;
    float4* hs4 = (float4*)hs;
    for (int j = tid; j < GROWS * 32; j += 128) {
        int r = j >> 5, q = j & 31;
        int row = base + r;
        hs4[j] = (row < NN) ? hin4[row * 32 + q] : make_float4(0.f, 0.f, 0.f, 0.f);
    }
    __syncthreads();

    unsigned long long acc[GROWS];
#pragma unroll
    for (int r = 0; r < GROWS; r++) acc[r] = 0ull;

    for (int kq = 0; kq < 32; kq++) {  // 4 K-values per iteration
        int k0 = 4 * kq;
        float w0 = __ldg(&W[(k0 + 0) * HID + tid]);
        float w1 = __ldg(&W[(k0 + 1) * HID + tid]);
        float w2 = __ldg(&W[(k0 + 2) * HID + tid]);
        float w3 = __ldg(&W[(k0 + 3) * HID + tid]);
        unsigned long long b01 = pack_f32x2(w0, w1);
        unsigned long long b23 = pack_f32x2(w2, w3);
#pragma unroll
        for (int r = 0; r < GROWS; r++) {
            const ulonglong2 a = *(const ulonglong2*)&hs[r * HID + k0];
            FMA_F32X2(acc[r], a.x, b01, acc[r]);
            FMA_F32X2(acc[r], a.y, b23, acc[r]);
        }
    }
    __syncthreads();  // done reading input tile; reuse hs for outputs
#pragma unroll
    for (int r = 0; r < GROWS; r++) {
        float lo, hi;
        unpack_f32x2(acc[r], lo, hi);
        float v = lo + hi;
        hs[r * HID + tid] = v;
        if (base + r < NN) g_h16[(base + r) * HID + tid] = __float2half(v);
    }
    __syncthreads();
    // scores: 4 warps x 8 rows each
    int wid = tid >> 5, lane = tid & 31;
    float4 s4 = ((const float4*)a_s)[lane];
    float4 d4 = ((const float4*)a_d)[lane];
#pragma unroll
    for (int i = 0; i < 8; i++) {
        int r = wid * 8 + i;
        float4 hv = ((const float4*)(hs + r * HID))[lane];
        float ps = hv.x * s4.x + hv.y * s4.y + hv.z * s4.z + hv.w * s4.w;
        float pd = hv.x * d4.x + hv.y * d4.y + hv.z * d4.z + hv.w * d4.w;
        ps = warp_sum(ps);
        pd = warp_sum(pd);
        if (lane == 0 && base + r < NN) { g_as[base + r] = ps; g_ad[base + r] = pd; }
    }
}

// ---------------- 128-dim softmax aggregation, single pass ------------------
// alpha = exp(e)/sum exp(e) (identical to max-subtracted softmax; clamp keeps
// exp finite). Gathers fp16 rows (256B/edge), accumulates fp32. -> g_hB
__global__ void agg128_kernel(const float* __restrict__ bias) {
    int warp = (blockIdx.x * blockDim.x + threadIdx.x) >> 5;
    int lane = threadIdx.x & 31;
    if (warp >= NN) return;
    int e = g_roff[warp], end = g_roff[warp + 1];
    float adi = g_ad[warp];

    float s = 0.f;
    float4 acc = make_float4(0.f, 0.f, 0.f, 0.f);
    for (; e + 3 < end; e += 4) {
        int s0 = g_csr[e], s1 = g_csr[e + 1], s2 = g_csr[e + 2], s3 = g_csr[e + 3];
        uint2 u0 = ((const uint2*)(g_h16 + s0 * HID))[lane];
        uint2 u1 = ((const uint2*)(g_h16 + s1 * HID))[lane];
        uint2 u2 = ((const uint2*)(g_h16 + s2 * HID))[lane];
        uint2 u3 = ((const uint2*)(g_h16 + s3 * HID))[lane];
        float w0 = __expf(fminf(lrelu(g_as[s0] + adi), 80.f));
        float w1 = __expf(fminf(lrelu(g_as[s1] + adi), 80.f));
        float w2 = __expf(fminf(lrelu(g_as[s2] + adi), 80.f));
        float w3 = __expf(fminf(lrelu(g_as[s3] + adi), 80.f));
        s += (w0 + w1) + (w2 + w3);
        float2 a0 = __half22float2(*(__half2*)&u0.x), b0 = __half22float2(*(__half2*)&u0.y);
        float2 a1 = __half22float2(*(__half2*)&u1.x), b1 = __half22float2(*(__half2*)&u1.y);
        float2 a2 = __half22float2(*(__half2*)&u2.x), b2 = __half22float2(*(__half2*)&u2.y);
        float2 a3 = __half22float2(*(__half2*)&u3.x), b3 = __half22float2(*(__half2*)&u3.y);
        acc.x += w0 * a0.x + w1 * a1.x + w2 * a2.x + w3 * a3.x;
        acc.y += w0 * a0.y + w1 * a1.y + w2 * a2.y + w3 * a3.y;
        acc.z += w0 * b0.x + w1 * b1.x + w2 * b2.x + w3 * b3.x;
        acc.w += w0 * b0.y + w1 * b1.y + w2 * b2.y + w3 * b3.y;
    }
    for (; e < end; e++) {
        int s0 = g_csr[e];
        uint2 u0 = ((const uint2*)(g_h16 + s0 * HID))[lane];
        float w0 = __expf(fminf(lrelu(g_as[s0] + adi), 80.f));
        s += w0;
        float2 a0 = __half22float2(*(__half2*)&u0.x), b0 = __half22float2(*(__half2*)&u0.y);
        acc.x += w0 * a0.x; acc.y += w0 * a0.y;
        acc.z += w0 * b0.x; acc.w += w0 * b0.y;
    }

    float inv = 1.f / s;
    // lane covers columns 4*lane..4*lane+3
    float4 b4 = ((const float4*)bias)[lane];
    acc.x = fmaxf(acc.x * inv + b4.x, 0.f);
    acc.y = fmaxf(acc.y * inv + b4.y, 0.f);
    acc.z = fmaxf(acc.z * inv + b4.z, 0.f);
    acc.w = fmaxf(acc.w * inv + b4.w, 0.f);
    ((float4*)g_hB)[warp * 32 + lane] = acc;
}

// ---------------- layer 3 GEMM (128->5) fused with scores -------------------
__global__ void l3_kernel(const float* __restrict__ W3,
                          const float* __restrict__ a_s, const float* __restrict__ a_d) {
    __shared__ float Ws[HID * OUTD];
    int tid = threadIdx.x;
    for (int j = tid; j < HID * OUTD; j += blockDim.x) Ws[j] = W3[j];
    __syncthreads();
    int warp = (blockIdx.x * blockDim.x + tid) >> 5;
    int lane = tid & 31;
    if (warp >= NN) return;
    const float4* h4 = (const float4*)g_hB;
    float4 hv = h4[warp * 32 + lane];
    int k = 4 * lane;
    float o[OUTD];
#pragma unroll
    for (int c = 0; c < OUTD; c++) {
        float p = hv.x * Ws[(k + 0) * OUTD + c] + hv.y * Ws[(k + 1) * OUTD + c]
                + hv.z * Ws[(k + 2) * OUTD + c] + hv.w * Ws[(k + 3) * OUTD + c];
        o[c] = warp_sum(p);
    }
    if (lane == 0) {
        float as = 0.f, ad = 0.f;
#pragma unroll
        for (int c = 0; c < OUTD; c++) {
            g_h3[warp * OUTD + c] = o[c];
            as += o[c] * a_s[c];
            ad += o[c] * a_d[c];
        }
        g_as[warp] = as;
        g_ad[warp] = ad;
    }
}

// ---------------- 5-dim aggregation + log_softmax -> d_out ------------------
__global__ void agg5_kernel(const float* __restrict__ b3, float* __restrict__ out) {
    int warp = (blockIdx.x * blockDim.x + threadIdx.x) >> 5;
    int lane = threadIdx.x & 31;
    if (warp >= NN) return;
    int e = g_roff[warp], end = g_roff[warp + 1];
    float adi = g_ad[warp];

    float s = 0.f, acc = 0.f;
    for (; e + 1 < end; e += 2) {
        int s0 = g_csr[e], s1 = g_csr[e + 1];
        float w0 = __expf(fminf(lrelu(g_as[s0] + adi), 80.f));
        float w1 = __expf(fminf(lrelu(g_as[s1] + adi), 80.f));
        s += w0 + w1;
        if (lane < OUTD) acc += w0 * g_h3[s0 * OUTD + lane] + w1 * g_h3[s1 * OUTD + lane];
    }
    if (e < end) {
        int s0 = g_csr[e];
        float w0 = __expf(fminf(lrelu(g_as[s0] + adi), 80.f));
        s += w0;
        if (lane < OUTD) acc += w0 * g_h3[s0 * OUTD + lane];
    }

    float v = (lane < OUTD) ? (acc / s + b3[lane]) : -1e30f;
    float m5 = v;
#pragma unroll
    for (int o = 4; o > 0; o >>= 1) m5 = fmaxf(m5, __shfl_xor_sync(0xffffffffu, m5, o));
    float ex = (lane < OUTD) ? __expf(v - m5) : 0.f;
#pragma unroll
    for (int o = 4; o > 0; o >>= 1) ex += __shfl_xor_sync(0xffffffffu, ex, o);
    if (lane < OUTD) out[warp * OUTD + lane] = v - m5 - logf(ex);
}

// ---------------- launch ----------------------------------------------------
extern "C" void kernel_launch(void* const* d_in, const int* in_sizes, int n_in,
                              void* d_out, int out_size) {
    const float* x      = (const float*)d_in[0];
    const void*  ei     = d_in[1];
    const float* W1     = (const float*)d_in[2];
    const float* a_src1 = (const float*)d_in[3];
    const float* a_dst1 = (const float*)d_in[4];
    const float* b1     = (const float*)d_in[5];
    const float* W2     = (const float*)d_in[6];
    const float* a_src2 = (const float*)d_in[7];
    const float* a_dst2 = (const float*)d_in[8];
    const float* b2     = (const float*)d_in[9];
    const float* W3     = (const float*)d_in[10];
    const float* a_src3 = (const float*)d_in[11];
    const float* a_dst3 = (const float*)d_in[12];
    const float* b3     = (const float*)d_in[13];
    float* out = (float*)d_out;

    const int E = in_sizes[1] / 2;
    const int N = NN;

    // CSR build
    init_kernel<<<NB, 256>>>((const unsigned*)ei, N);
    convert_count_kernel<<<(E + 255) / 256, 256>>>(ei, E);
    scan1_kernel<<<NB, 256>>>();
    scan2_kernel<<<1, 256>>>(E);
    scan3_kernel<<<NB, 256>>>();
    scatter_kernel<<<(N + E + 255) / 256, 256>>>(E, N);

    // Layer 1
    gemm13_kernel<<<N / 16, 128>>>(x, W1, a_src1, a_dst1);
    agg128_kernel<<<N / 8, 256>>>(b1);

    // Layer 2
    gemm128_kernel<<<(N + GROWS - 1) / GROWS, 128>>>(W2, a_src2, a_dst2);
    agg128_kernel<<<N / 8, 256>>>(b2);

    // Layer 3
    l3_kernel<<<N / 8, 256>>>(W3, a_src3, a_dst3);
    agg5_kernel<<<N / 8, 256>>>(b3, out);
}

// round 10
// speedup vs baseline: 1.5786x; 1.0922x over previous
#include <cuda_runtime.h>
#include <cuda_fp16.h>

// GAT 3-layer forward on GB300.
// CSR-by-dst build (packed (src,dst) per slot), per layer: dense GEMM with
// fused score epilogue (fp16 features + fp32 scores), edge-parallel softmax
// weight precompute, then warp-per-node aggregation with half-warp-per-edge
// uint4 gathers (one LDG.128 per edge row) and fp32 accumulation.

#define NN   50000
#define EE   1600000
#define ET   (NN + EE)     // edges + self loops
#define HID  128
#define IND  13
#define OUTD 5
#define NB   196           // ceil(NN/256)

// ---------------- scratch (device globals; no allocation allowed) ----------
__device__ __align__(16) __half g_h16[NN * HID];  // fp16 features for gathers
__device__ __align__(16) float g_hB[NN * HID];    // fp32 agg outputs / GEMM inputs
__device__ __align__(16) float g_h3[NN * OUTD];
__device__ float g_as[NN];
__device__ float g_ad[NN];
__device__ int   g_deg[NN];
__device__ int   g_roff[NN + 1];
__device__ int   g_cur[NN];
__device__ __align__(16) long long g_csrp[ET];    // packed: low=src, high=dst
__device__ __align__(16) float g_w[ET];           // per-edge softmax weight
__device__ int   g_srcv[EE];
__device__ int   g_dstv[EE];
__device__ int   g_bsum[256];
__device__ int   g_boff[256];
__device__ int   g_is64;

#define FMA_F32X2(d, a, b, c) \
    asm("fma.rn.f32x2 %0, %1, %2, %3;" : "=l"(d) : "l"(a), "l"(b), "l"(c))

__device__ __forceinline__ unsigned long long pack_f32x2(float lo, float hi) {
    unsigned long long r;
    unsigned ulo = __float_as_uint(lo), uhi = __float_as_uint(hi);
    asm("mov.b64 %0, {%1, %2};" : "=l"(r) : "r"(ulo), "r"(uhi));
    return r;
}
__device__ __forceinline__ void unpack_f32x2(unsigned long long v, float& lo, float& hi) {
    unsigned ulo, uhi;
    asm("mov.b64 {%0, %1}, %2;" : "=r"(ulo), "=r"(uhi) : "l"(v));
    lo = __uint_as_float(ulo);
    hi = __uint_as_float(uhi);
}

__device__ __forceinline__ float warp_sum(float v) {
#pragma unroll
    for (int o = 16; o > 0; o >>= 1) v += __shfl_xor_sync(0xffffffffu, v, o);
    return v;
}
__device__ __forceinline__ float lrelu(float v) { return v > 0.f ? v : 0.2f * v; }

// ---------------- detect edge dtype + init degrees (fused) ------------------
__global__ void init_kernel(const unsigned* __restrict__ w, int n) {
    int i = blockIdx.x * blockDim.x + threadIdx.x;
    if (i < n) g_deg[i] = 1;  // self loop
    if (blockIdx.x == 0 && threadIdx.x == 0) {
        int all0 = 1;
        for (int k = 1; k < 64; k += 2) all0 &= (w[k] == 0u);
        g_is64 = all0;
    }
}

__global__ void convert_count_kernel(const void* __restrict__ ei, int E) {
    int i = blockIdx.x * blockDim.x + threadIdx.x;
    if (i >= E) return;
    int s, d;
    if (g_is64) {
        const long long* p = (const long long*)ei;
        s = (int)p[i];
        d = (int)p[E + i];
    } else {
        const int* p = (const int*)ei;
        s = p[i];
        d = p[E + i];
    }
    g_srcv[i] = s;
    g_dstv[i] = d;
    atomicAdd(&g_deg[d], 1);
}

// ---------------- two-level parallel exclusive scan of g_deg ----------------
__global__ void scan1_kernel() {
    int i = blockIdx.x * 256 + threadIdx.x;
    int v = (i < NN) ? g_deg[i] : 0;
#pragma unroll
    for (int o = 16; o > 0; o >>= 1) v += __shfl_xor_sync(0xffffffffu, v, o);
    __shared__ int sw[8];
    if ((threadIdx.x & 31) == 0) sw[threadIdx.x >> 5] = v;
    __syncthreads();
    if (threadIdx.x == 0) {
        int t = 0;
#pragma unroll
        for (int k = 0; k < 8; k++) t += sw[k];
        g_bsum[blockIdx.x] = t;
    }
}

__global__ void scan2_kernel(int E) {
    __shared__ int sh[256];
    int tid = threadIdx.x;
    int v = (tid < NB) ? g_bsum[tid] : 0;
    sh[tid] = v;
    __syncthreads();
    for (int off = 1; off < 256; off <<= 1) {
        int t = (tid >= off) ? sh[tid - off] : 0;
        __syncthreads();
        sh[tid] += t;
        __syncthreads();
    }
    g_boff[tid] = sh[tid] - v;  // exclusive
    if (tid == 0) g_roff[NN] = NN + E;
}

__global__ void scan3_kernel() {
    __shared__ int sh[256];
    int tid = threadIdx.x;
    int i = blockIdx.x * 256 + tid;
    int v = (i < NN) ? g_deg[i] : 0;
    sh[tid] = v;
    __syncthreads();
    for (int off = 1; off < 256; off <<= 1) {
        int t = (tid >= off) ? sh[tid - off] : 0;
        __syncthreads();
        sh[tid] += t;
        __syncthreads();
    }
    if (i < NN) {
        int o = g_boff[blockIdx.x] + sh[tid] - v;
        g_roff[i] = o;
        g_cur[i]  = o;
    }
}

__global__ void scatter_kernel(int E, int n) {
    int i = blockIdx.x * blockDim.x + threadIdx.x;
    int total = n + E;
    if (i >= total) return;
    int src, dst;
    if (i < n) { src = i; dst = i; }
    else       { int e = i - n; src = g_srcv[e]; dst = g_dstv[e]; }
    int p = atomicAdd(&g_cur[dst], 1);
    g_csrp[p] = (long long)(unsigned)src | ((long long)dst << 32);
}

// ---------------- per-edge softmax weights (streaming, per layer) -----------
__global__ void weights_kernel(int total) {
    int i = blockIdx.x * blockDim.x + threadIdx.x;
    if (i >= total) return;
    long long v = g_csrp[i];
    int s = (int)v;
    int d = (int)(v >> 32);
    g_w[i] = __expf(fminf(lrelu(g_as[s] + g_ad[d]), 80.f));
}

// ---------------- GEMMs with fused score epilogue ---------------------------
// Layer 1: [N,13] @ [13,128] -> g_h16 (+ scores g_as/g_ad)
__global__ void gemm13_kernel(const float* __restrict__ x, const float* __restrict__ W,
                              const float* __restrict__ a_s, const float* __restrict__ a_d) {
    __shared__ float Ws[IND * HID];
    __shared__ float xs[16 * IND];
    __shared__ __align__(16) float hs[16 * HID];
    int tid = threadIdx.x;
    for (int j = tid; j < IND * HID; j += 128) Ws[j] = W[j];
    int base = blockIdx.x * 16;
    for (int j = tid; j < 16 * IND; j += 128) {
        int r = j / IND, k = j % IND;
        xs[j] = x[(base + r) * IND + k];
    }
    __syncthreads();
#pragma unroll 4
    for (int r = 0; r < 16; r++) {
        float acc = 0.f;
#pragma unroll
        for (int k = 0; k < IND; k++) acc += xs[r * IND + k] * Ws[k * HID + tid];
        g_h16[(base + r) * HID + tid] = __float2half(acc);
        hs[r * HID + tid] = acc;
    }
    __syncthreads();
    // scores: 4 warps x 4 rows each
    int wid = tid >> 5, lane = tid & 31;
    float4 s4 = ((const float4*)a_s)[lane];
    float4 d4 = ((const float4*)a_d)[lane];
#pragma unroll
    for (int i = 0; i < 4; i++) {
        int r = wid * 4 + i;
        float4 hv = ((const float4*)(hs + r * HID))[lane];
        float ps = hv.x * s4.x + hv.y * s4.y + hv.z * s4.z + hv.w * s4.w;
        float pd = hv.x * d4.x + hv.y * d4.y + hv.z * d4.z + hv.w * d4.w;
        ps = warp_sum(ps);
        pd = warp_sum(pd);
        if (lane == 0) { g_as[base + r] = ps; g_ad[base + r] = pd; }
    }
}

// Layer 2: g_hB [N,128] @ W2 [128,128] -> g_h16 (+ scores).
#define GROWS 32
__global__ void __launch_bounds__(128) gemm128_kernel(const float* __restrict__ W,
                                                      const float* __restrict__ a_s,
                                                      const float* __restrict__ a_d) {
    __shared__ __align__(16) float hs[GROWS * HID];  // 16KB, reused for epilogue
    int tid = threadIdx.x;
    int base = blockIdx.x * GROWS;
    const float4* hin4 = (const float4*)g_hB;
    float4* hs4 = (float4*)hs;
    for (int j = tid; j < GROWS * 32; j += 128) {
        int r = j >> 5, q = j & 31;
        int row = base + r;
        hs4[j] = (row < NN) ? hin4[row * 32 + q] : make_float4(0.f, 0.f, 0.f, 0.f);
    }
    __syncthreads();

    unsigned long long acc[GROWS];
#pragma unroll
    for (int r = 0; r < GROWS; r++) acc[r] = 0ull;

    for (int kq = 0; kq < 32; kq++) {  // 4 K-values per iteration
        int k0 = 4 * kq;
        float w0 = __ldg(&W[(k0 + 0) * HID + tid]);
        float w1 = __ldg(&W[(k0 + 1) * HID + tid]);
        float w2 = __ldg(&W[(k0 + 2) * HID + tid]);
        float w3 = __ldg(&W[(k0 + 3) * HID + tid]);
        unsigned long long b01 = pack_f32x2(w0, w1);
        unsigned long long b23 = pack_f32x2(w2, w3);
#pragma unroll
        for (int r = 0; r < GROWS; r++) {
            const ulonglong2 a = *(const ulonglong2*)&hs[r * HID + k0];
            FMA_F32X2(acc[r], a.x, b01, acc[r]);
            FMA_F32X2(acc[r], a.y, b23, acc[r]);
        }
    }
    __syncthreads();  // done reading input tile; reuse hs for outputs
#pragma unroll
    for (int r = 0; r < GROWS; r++) {
        float lo, hi;
        unpack_f32x2(acc[r], lo, hi);
        float v = lo + hi;
        hs[r * HID + tid] = v;
        if (base + r < NN) g_h16[(base + r) * HID + tid] = __float2half(v);
    }
    __syncthreads();
    // scores: 4 warps x 8 rows each
    int wid = tid >> 5, lane = tid & 31;
    float4 s4 = ((const float4*)a_s)[lane];
    float4 d4 = ((const float4*)a_d)[lane];
#pragma unroll
    for (int i = 0; i < 8; i++) {
        int r = wid * 8 + i;
        float4 hv = ((const float4*)(hs + r * HID))[lane];
        float ps = hv.x * s4.x + hv.y * s4.y + hv.z * s4.z + hv.w * s4.w;
        float pd = hv.x * d4.x + hv.y * d4.y + hv.z * d4.z + hv.w * d4.w;
        ps = warp_sum(ps);
        pd = warp_sum(pd);
        if (lane == 0 && base + r < NN) { g_as[base + r] = ps; g_ad[base + r] = pd; }
    }
}

// ---------------- 128-dim aggregation: half-warp per edge -------------------
// 16 lanes x uint4 (16B) cover one 256B fp16 row -> warp gathers 2 edges per
// LDG.128. Weights precomputed (g_w). alpha = w/sum(w). -> g_hB
__global__ void agg128_kernel(const float* __restrict__ bias) {
    int warp = (blockIdx.x * blockDim.x + threadIdx.x) >> 5;
    int lane = threadIdx.x & 31;
    if (warp >= NN) return;
    int e0 = g_roff[warp], e1 = g_roff[warp + 1];
    int half = lane >> 4;   // which edge of the pair this lane handles
    int l16  = lane & 15;

    float acc[8];
#pragma unroll
    for (int j = 0; j < 8; j++) acc[j] = 0.f;
    float s = 0.f;

    int e = e0;
    for (; e + 7 < e1; e += 8) {
#pragma unroll
        for (int p = 0; p < 4; p++) {
            int idx = e + 2 * p + half;
            int src = *(const int*)(g_csrp + idx);   // low word = src
            float w = g_w[idx];
            const uint4 u = ((const uint4*)(g_h16 + src * HID))[l16];
            s += w;
            float2 f0 = __half22float2(*(const __half2*)&u.x);
            float2 f1 = __half22float2(*(const __half2*)&u.y);
            float2 f2 = __half22float2(*(const __half2*)&u.z);
            float2 f3 = __half22float2(*(const __half2*)&u.w);
            acc[0] += w * f0.x; acc[1] += w * f0.y;
            acc[2] += w * f1.x; acc[3] += w * f1.y;
            acc[4] += w * f2.x; acc[5] += w * f2.y;
            acc[6] += w * f3.x; acc[7] += w * f3.y;
        }
    }
    for (; e < e1; e++) {  // remainder: one edge at a time, half 0 contributes
        int src = *(const int*)(g_csrp + e);
        float w = (half == 0) ? g_w[e] : 0.f;
        const uint4 u = ((const uint4*)(g_h16 + src * HID))[l16];
        s += w;
        float2 f0 = __half22float2(*(const __half2*)&u.x);
        float2 f1 = __half22float2(*(const __half2*)&u.y);
        float2 f2 = __half22float2(*(const __half2*)&u.z);
        float2 f3 = __half22float2(*(const __half2*)&u.w);
        acc[0] += w * f0.x; acc[1] += w * f0.y;
        acc[2] += w * f1.x; acc[3] += w * f1.y;
        acc[4] += w * f2.x; acc[5] += w * f2.y;
        acc[6] += w * f3.x; acc[7] += w * f3.y;
    }

    // fold half 1 into half 0
    s += __shfl_down_sync(0xffffffffu, s, 16);
#pragma unroll
    for (int j = 0; j < 8; j++) acc[j] += __shfl_down_sync(0xffffffffu, acc[j], 16);

    if (lane < 16) {
        float inv = 1.f / s;
        const float4* b4 = (const float4*)(bias + l16 * 8);
        float4 bA = b4[0], bB = b4[1];
        float4 oA, oB;
        oA.x = fmaxf(acc[0] * inv + bA.x, 0.f);
        oA.y = fmaxf(acc[1] * inv + bA.y, 0.f);
        oA.z = fmaxf(acc[2] * inv + bA.z, 0.f);
        oA.w = fmaxf(acc[3] * inv + bA.w, 0.f);
        oB.x = fmaxf(acc[4] * inv + bB.x, 0.f);
        oB.y = fmaxf(acc[5] * inv + bB.y, 0.f);
        oB.z = fmaxf(acc[6] * inv + bB.z, 0.f);
        oB.w = fmaxf(acc[7] * inv + bB.w, 0.f);
        float4* dst = (float4*)(g_hB + warp * HID + l16 * 8);
        dst[0] = oA;
        dst[1] = oB;
    }
}

// ---------------- layer 3 GEMM (128->5) fused with scores -------------------
__global__ void l3_kernel(const float* __restrict__ W3,
                          const float* __restrict__ a_s, const float* __restrict__ a_d) {
    __shared__ float Ws[HID * OUTD];
    int tid = threadIdx.x;
    for (int j = tid; j < HID * OUTD; j += blockDim.x) Ws[j] = W3[j];
    __syncthreads();
    int warp = (blockIdx.x * blockDim.x + tid) >> 5;
    int lane = tid & 31;
    if (warp >= NN) return;
    const float4* h4 = (const float4*)g_hB;
    float4 hv = h4[warp * 32 + lane];
    int k = 4 * lane;
    float o[OUTD];
#pragma unroll
    for (int c = 0; c < OUTD; c++) {
        float p = hv.x * Ws[(k + 0) * OUTD + c] + hv.y * Ws[(k + 1) * OUTD + c]
                + hv.z * Ws[(k + 2) * OUTD + c] + hv.w * Ws[(k + 3) * OUTD + c];
        o[c] = warp_sum(p);
    }
    if (lane == 0) {
        float as = 0.f, ad = 0.f;
#pragma unroll
        for (int c = 0; c < OUTD; c++) {
            g_h3[warp * OUTD + c] = o[c];
            as += o[c] * a_s[c];
            ad += o[c] * a_d[c];
        }
        g_as[warp] = as;
        g_ad[warp] = ad;
    }
}

// ---------------- 5-dim aggregation + log_softmax -> d_out ------------------
__global__ void agg5_kernel(const float* __restrict__ b3, float* __restrict__ out) {
    int warp = (blockIdx.x * blockDim.x + threadIdx.x) >> 5;
    int lane = threadIdx.x & 31;
    if (warp >= NN) return;
    int e = g_roff[warp], end = g_roff[warp + 1];

    float s = 0.f, acc = 0.f;
    for (; e + 1 < end; e += 2) {
        int s0 = *(const int*)(g_csrp + e);
        int s1 = *(const int*)(g_csrp + e + 1);
        float w0 = g_w[e], w1 = g_w[e + 1];
        s += w0 + w1;
        if (lane < OUTD) acc += w0 * g_h3[s0 * OUTD + lane] + w1 * g_h3[s1 * OUTD + lane];
    }
    if (e < end) {
        int s0 = *(const int*)(g_csrp + e);
        float w0 = g_w[e];
        s += w0;
        if (lane < OUTD) acc += w0 * g_h3[s0 * OUTD + lane];
    }

    float v = (lane < OUTD) ? (acc / s + b3[lane]) : -1e30f;
    float m5 = v;
#pragma unroll
    for (int o = 4; o > 0; o >>= 1) m5 = fmaxf(m5, __shfl_xor_sync(0xffffffffu, m5, o));
    float ex = (lane < OUTD) ? __expf(v - m5) : 0.f;
#pragma unroll
    for (int o = 4; o > 0; o >>= 1) ex += __shfl_xor_sync(0xffffffffu, ex, o);
    if (lane < OUTD) out[warp * OUTD + lane] = v - m5 - logf(ex);
}

// ---------------- launch ----------------------------------------------------
extern "C" void kernel_launch(void* const* d_in, const int* in_sizes, int n_in,
                              void* d_out, int out_size) {
    const float* x      = (const float*)d_in[0];
    const void*  ei     = d_in[1];
    const float* W1     = (const float*)d_in[2];
    const float* a_src1 = (const float*)d_in[3];
    const float* a_dst1 = (const float*)d_in[4];
    const float* b1     = (const float*)d_in[5];
    const float* W2     = (const float*)d_in[6];
    const float* a_src2 = (const float*)d_in[7];
    const float* a_dst2 = (const float*)d_in[8];
    const float* b2     = (const float*)d_in[9];
    const float* W3     = (const float*)d_in[10];
    const float* a_src3 = (const float*)d_in[11];
    const float* a_dst3 = (const float*)d_in[12];
    const float* b3     = (const float*)d_in[13];
    float* out = (float*)d_out;

    const int E = in_sizes[1] / 2;
    const int N = NN;
    const int total = N + E;

    // CSR build
    init_kernel<<<NB, 256>>>((const unsigned*)ei, N);
    convert_count_kernel<<<(E + 255) / 256, 256>>>(ei, E);
    scan1_kernel<<<NB, 256>>>();
    scan2_kernel<<<1, 256>>>(E);
    scan3_kernel<<<NB, 256>>>();
    scatter_kernel<<<(total + 255) / 256, 256>>>(E, N);

    // Layer 1
    gemm13_kernel<<<N / 16, 128>>>(x, W1, a_src1, a_dst1);
    weights_kernel<<<(total + 255) / 256, 256>>>(total);
    agg128_kernel<<<N / 8, 256>>>(b1);

    // Layer 2
    gemm128_kernel<<<(N + GROWS - 1) / GROWS, 128>>>(W2, a_src2, a_dst2);
    weights_kernel<<<(total + 255) / 256, 256>>>(total);
    agg128_kernel<<<N / 8, 256>>>(b2);

    // Layer 3
    l3_kernel<<<N / 8, 256>>>(W3, a_src3, a_dst3);
    weights_kernel<<<(total + 255) / 256, 256>>>(total);
    agg5_kernel<<<N / 8, 256>>>(b3, out);
}